// round 1
// baseline (speedup 1.0000x reference)
#include <cuda_runtime.h>
#include <cuda_bf16.h>
#include <mma.h>
#include <math.h>

using namespace nvcuda;

#define BATCH 8192
#define SDIM  376
#define ADIM  17
#define DIN   393     // state+action
#define DPAD  400     // padded K for GEMM1 (multiple of 16)
#define H1    400
#define H2    300
#define TSTEPS 32

#define CAPC  24      // firing W2 rows cached in smem per batch-row
#define CAP1  96      // per-timestep layer-1 firing list capacity
#define CAP2  96      // per-timestep layer-2 firing list capacity

// ---------------- static device scratch (no allocations) ----------------
__device__ __align__(16) __nv_bfloat16 g_A[BATCH * DPAD];      // packed bf16 input
__device__ __align__(16) __nv_bfloat16 g_W1b[DPAD * H1];       // packed bf16 W1 (K-padded)
__device__ __align__(16) float         g_X1[(size_t)BATCH * H1];
__device__ __align__(16) unsigned      g_S1[(size_t)BATCH * H1]; // layer-1 spike bitmasks

// ---------------- K0a: pack [state|action|0pad] -> bf16 ----------------
__global__ void k_pack_input(const float* __restrict__ state,
                             const float* __restrict__ action) {
    int idx = blockIdx.x * blockDim.x + threadIdx.x;
    if (idx >= BATCH * DPAD) return;
    int row = idx / DPAD;
    int col = idx - row * DPAD;
    float v = 0.0f;
    if (col < SDIM)      v = state[(size_t)row * SDIM + col];
    else if (col < DIN)  v = action[(size_t)row * ADIM + (col - SDIM)];
    g_A[idx] = __float2bfloat16(v);
}

// ---------------- K0b: pack W1 (393x400 -> 400x400, zero pad) ----------------
__global__ void k_pack_w1(const float* __restrict__ W1) {
    int idx = blockIdx.x * blockDim.x + threadIdx.x;
    if (idx >= DPAD * H1) return;
    int r = idx / H1;
    int c = idx - r * H1;
    g_W1b[idx] = __float2bfloat16(r < DIN ? W1[(size_t)r * H1 + c] : 0.0f);
}

// ---------------- K1: X1 = A @ W1  (bf16 wmma, fp32 accum) ----------------
// grid (5, 64): 80-col x 128-row tiles; 8 warps; warp owns 16 rows x 80 cols.
__global__ __launch_bounds__(256) void k_gemm1() {
    __shared__ __align__(16) __nv_bfloat16 sA[128 * 16];
    __shared__ __align__(16) __nv_bfloat16 sB[16 * 80];

    int tid = threadIdx.x;
    int w   = tid >> 5;
    int m0  = blockIdx.y * 128;
    int n0  = blockIdx.x * 80;

    wmma::fragment<wmma::accumulator, 16, 16, 16, float> acc[5];
#pragma unroll
    for (int f = 0; f < 5; f++) wmma::fill_fragment(acc[f], 0.0f);

    for (int k0 = 0; k0 < DPAD; k0 += 16) {
        // load A tile 128x16 (one uint4 = 8 bf16 per thread)
        {
            int r = tid >> 1, h = tid & 1;
            const uint4* src = reinterpret_cast<const uint4*>(
                &g_A[(size_t)(m0 + r) * DPAD + k0 + 8 * h]);
            *reinterpret_cast<uint4*>(&sA[r * 16 + 8 * h]) = *src;
        }
        // load B tile 16x80
        if (tid < 160) {
            int r = tid / 10, p = tid % 10;
            const uint4* src = reinterpret_cast<const uint4*>(
                &g_W1b[(size_t)(k0 + r) * H1 + n0 + 8 * p]);
            *reinterpret_cast<uint4*>(&sB[r * 80 + 8 * p]) = *src;
        }
        __syncthreads();

        wmma::fragment<wmma::matrix_a, 16, 16, 16, __nv_bfloat16, wmma::row_major> afrag;
        wmma::load_matrix_sync(afrag, &sA[w * 16 * 16], 16);
#pragma unroll
        for (int f = 0; f < 5; f++) {
            wmma::fragment<wmma::matrix_b, 16, 16, 16, __nv_bfloat16, wmma::row_major> bfrag;
            wmma::load_matrix_sync(bfrag, &sB[f * 16], 80);
            wmma::mma_sync(acc[f], afrag, bfrag, acc[f]);
        }
        __syncthreads();
    }
#pragma unroll
    for (int f = 0; f < 5; f++)
        wmma::store_matrix_sync(&g_X1[(size_t)(m0 + w * 16) * H1 + n0 + f * 16],
                                acc[f], H1, wmma::mem_row_major);
}

// ---------------- K1b: per-element LIF1 simulation -> 32-bit spike mask ------
__global__ void k_lif1(const float* __restrict__ b1) {
    int idx = blockIdx.x * blockDim.x + threadIdx.x;
    if (idx >= BATCH * H1) return;
    int col = idx % H1;
    float x = g_X1[idx] + b1[col];
    float v = 0.0f;
    unsigned word = 0u;
#pragma unroll
    for (int t = 0; t < TSTEPS; t++) {
        v += (x - v) * 0.5f;                 // v += (x - (v - v_reset))/tau
        if (v >= 1.0f) { word |= (1u << t); v = 0.0f; }
    }
    g_S1[idx] = word;
}

// ---------------- K2: one CTA per row: sparse layer2 + LIF2 + layer3 + out ---
__global__ __launch_bounds__(320) void k_snn(const float* __restrict__ action,
                                             const float* __restrict__ W2,
                                             const float* __restrict__ b2,
                                             const float* __restrict__ W3,
                                             const float* __restrict__ b3,
                                             float* __restrict__ out) {
    __shared__ float          s_w2[CAPC * H2];       // cached firing W2 rows
    __shared__ unsigned       s_mask1[H1];
    __shared__ unsigned short s_fire[H1];            // compacted firing neuron ids
    __shared__ unsigned short s_list1[TSTEPS][CAP1]; // per-t firing (cache slot or 256+i)
    __shared__ int            s_cnt1[TSTEPS];
    __shared__ unsigned       s_mask2[H2];
    __shared__ unsigned short s_list2[TSTEPS][CAP2];
    __shared__ int            s_cnt2[TSTEPS];
    __shared__ int            s_nf;

    int row  = blockIdx.x;
    int tid  = threadIdx.x;
    int lane = tid & 31;
    int w    = tid >> 5;
    unsigned lmask = (1u << lane) - 1u;

    // 1) load layer-1 spike masks for this row
    for (int i = tid; i < H1; i += 320)
        s_mask1[i] = g_S1[(size_t)row * H1 + i];
    __syncthreads();

    // 2) warp 0: deterministic compaction of firing neurons (ordered by i)
    if (w == 0) {
        int nf = 0;
        for (int c = 0; c * 32 < H1; c++) {
            int i = c * 32 + lane;
            unsigned m = (i < H1) ? s_mask1[i] : 0u;
            int pred = (m != 0u);
            unsigned bal = __ballot_sync(0xffffffffu, pred);
            int pos = nf + __popc(bal & lmask);
            if (pred) s_fire[pos] = (unsigned short)i;
            nf += __popc(bal);
        }
        if (lane == 0) s_nf = nf;
    }
    __syncthreads();
    int nf = s_nf;
    int ncache = nf < CAPC ? nf : CAPC;

    // 3) cache W2 rows of firing neurons (coalesced: consecutive j)
    for (int idx = tid; idx < ncache * H2; idx += 320) {
        int q = idx / H2;
        int j = idx - q * H2;
        s_w2[q * H2 + j] = W2[(size_t)s_fire[q] * H2 + j];
    }

    // 4) per-timestep firing lists (deterministic ballot-compaction)
    for (int t = w; t < TSTEPS; t += 10) {
        int cnt = 0;
        for (int c = 0; c * 32 < nf; c++) {
            int qi = c * 32 + lane;
            int pred = 0; unsigned short entry = 0;
            if (qi < nf) {
                int i = s_fire[qi];
                if ((s_mask1[i] >> t) & 1u) {
                    pred = 1;
                    entry = (qi < CAPC) ? (unsigned short)qi
                                        : (unsigned short)(256 + i);
                }
            }
            unsigned bal = __ballot_sync(0xffffffffu, pred);
            int pos = cnt + __popc(bal & lmask);
            if (pred && pos < CAP1) s_list1[t][pos] = entry;
            cnt += __popc(bal);
        }
        s_cnt1[t] = cnt < CAP1 ? cnt : CAP1;
    }
    __syncthreads();

    // 5) layer 2: x2(t) sparse sum + LIF2 recurrence, per output neuron j
    if (tid < H2) {
        int j = tid;
        float b2j = b2[j];
        float v2 = 0.0f;
        unsigned mask2 = 0u;
        for (int t = 0; t < TSTEPS; t++) {
            float x2 = b2j;
            int n = s_cnt1[t];
            for (int q = 0; q < n; q++) {
                int e = s_list1[t][q];
                float wv = (e < CAPC) ? s_w2[e * H2 + j]
                                      : W2[(size_t)(e - 256) * H2 + j];
                x2 += wv;
            }
            v2 += (x2 - v2) * 0.5f;
            if (v2 >= 1.0f) { mask2 |= (1u << t); v2 = 0.0f; }
        }
        s_mask2[j] = mask2;
    }
    __syncthreads();

    // 6) per-timestep layer-2 firing lists
    for (int t = w; t < TSTEPS; t += 10) {
        int cnt = 0;
        for (int c = 0; c * 32 < H2; c++) {
            int j = c * 32 + lane;
            int pred = 0;
            if (j < H2) pred = (int)((s_mask2[j] >> t) & 1u);
            unsigned bal = __ballot_sync(0xffffffffu, pred);
            int pos = cnt + __popc(bal & lmask);
            if (pred && pos < CAP2) s_list2[t][pos] = (unsigned short)j;
            cnt += __popc(bal);
        }
        s_cnt2[t] = cnt < CAP2 ? cnt : CAP2;
    }
    __syncthreads();

    // 7) layer 3 (non-spiking LIF, max over t) + tanh/clip epilogue
    if (tid < ADIM) {
        int k = tid;
        float b3k = b3[k];
        float v3 = 0.0f, vmax = -3.4e38f;
        for (int t = 0; t < TSTEPS; t++) {
            float x3 = b3k;
            int n = s_cnt2[t];
            for (int q = 0; q < n; q++) {
                int j = s_list2[t][q];
                x3 += W3[j * ADIM + k];
            }
            v3 += (x3 - v3) * 0.5f;
            vmax = fmaxf(vmax, v3);
        }
        float a = 0.05f * tanhf(vmax);              // PHI * MAX_ACTION * tanh
        float o = a + action[(size_t)row * ADIM + k];
        o = fminf(fmaxf(o, -1.0f), 1.0f);
        out[(size_t)row * ADIM + k] = o;
    }
}

// ---------------- launch ----------------
extern "C" void kernel_launch(void* const* d_in, const int* in_sizes, int n_in,
                              void* d_out, int out_size) {
    (void)in_sizes; (void)n_in; (void)out_size;
    const float* state  = (const float*)d_in[0];
    const float* action = (const float*)d_in[1];
    const float* W1     = (const float*)d_in[2];
    const float* b1     = (const float*)d_in[3];
    const float* W2     = (const float*)d_in[4];
    const float* b2     = (const float*)d_in[5];
    const float* W3     = (const float*)d_in[6];
    const float* b3     = (const float*)d_in[7];
    float* out = (float*)d_out;

    k_pack_input<<<(BATCH * DPAD + 255) / 256, 256>>>(state, action);
    k_pack_w1<<<(DPAD * H1 + 255) / 256, 256>>>(W1);

    dim3 g1(5, 64);                 // N=400/80, M=8192/128
    k_gemm1<<<g1, 256>>>();

    k_lif1<<<(BATCH * H1 + 255) / 256, 256>>>(b1);

    k_snn<<<BATCH, 320>>>(action, W2, b2, W3, b3, out);
}

// round 2
// speedup vs baseline: 2.5866x; 2.5866x over previous
#include <cuda_runtime.h>
#include <cuda_bf16.h>
#include <mma.h>
#include <math.h>

using namespace nvcuda;

#define BATCH 8192
#define SDIM  376
#define ADIM  17
#define DIN   393
#define DPAD  400
#define H1    400
#define H2    300
#define TSTEPS 32

#define CAPC  24
#define CAP1  96
#define CAP2  96

// ---------------- static device scratch ----------------
__device__ __align__(16) __nv_bfloat16 g_A[BATCH * DPAD];
__device__ __align__(16) __nv_bfloat16 g_W1b[DPAD * H1];
__device__ __align__(16) float         g_X1[(size_t)BATCH * H1];
__device__ __align__(16) unsigned      g_S1[(size_t)BATCH * H1];
__device__ float    g_c[H1];          // c_i = max_j W2[i,j]
__device__ float    g_b2max;
__device__ float    g_const[ADIM];    // 0.05*tanh(vmax(b3_k))
__device__ int      g_flag[BATCH];    // 0 = fast (no layer-2 spikes possible), 1 = slow

// ---------------- K0a: pack [state|action|0pad] -> bf16 ----------------
__global__ void k_pack_input(const float* __restrict__ state,
                             const float* __restrict__ action) {
    int idx = blockIdx.x * blockDim.x + threadIdx.x;
    if (idx >= BATCH * DPAD) return;
    int row = idx / DPAD;
    int col = idx - row * DPAD;
    float v = 0.0f;
    if (col < SDIM)      v = state[(size_t)row * SDIM + col];
    else if (col < DIN)  v = action[(size_t)row * ADIM + (col - SDIM)];
    g_A[idx] = __float2bfloat16(v);
}

// ---------------- K0b: pack W1 ----------------
__global__ void k_pack_w1(const float* __restrict__ W1) {
    int idx = blockIdx.x * blockDim.x + threadIdx.x;
    if (idx >= DPAD * H1) return;
    int r = idx / H1;
    int c = idx - r * H1;
    g_W1b[idx] = __float2bfloat16(r < DIN ? W1[(size_t)r * H1 + c] : 0.0f);
}

// ---------------- K_prep: c_i, b2max, const_k ----------------
__global__ void k_prep(const float* __restrict__ W2,
                       const float* __restrict__ b2,
                       const float* __restrict__ b3) {
    int bid  = blockIdx.x;
    int lane = threadIdx.x;
    if (bid < H1) {
        float m = -3.4e38f;
        for (int j = lane; j < H2; j += 32)
            m = fmaxf(m, W2[(size_t)bid * H2 + j]);
#pragma unroll
        for (int o = 16; o; o >>= 1) m = fmaxf(m, __shfl_xor_sync(0xffffffffu, m, o));
        if (lane == 0) g_c[bid] = m;
    } else {
        float m = -3.4e38f;
        for (int j = lane; j < H2; j += 32) m = fmaxf(m, b2[j]);
#pragma unroll
        for (int o = 16; o; o >>= 1) m = fmaxf(m, __shfl_xor_sync(0xffffffffu, m, o));
        if (lane == 0) g_b2max = m;
        if (lane < ADIM) {
            float b = b3[lane];
            float vmax = (b > 0.0f) ? b : 0.5f * b;   // monotone v3 = b3*(1-2^-t)
            g_const[lane] = 0.05f * tanhf(vmax);
        }
    }
}

// ---------------- K1: X1 = A @ W1 (bf16 wmma) ----------------
__global__ __launch_bounds__(256) void k_gemm1() {
    __shared__ __align__(16) __nv_bfloat16 sA[128 * 16];
    __shared__ __align__(16) __nv_bfloat16 sB[16 * 80];

    int tid = threadIdx.x;
    int w   = tid >> 5;
    int m0  = blockIdx.y * 128;
    int n0  = blockIdx.x * 80;

    wmma::fragment<wmma::accumulator, 16, 16, 16, float> acc[5];
#pragma unroll
    for (int f = 0; f < 5; f++) wmma::fill_fragment(acc[f], 0.0f);

    for (int k0 = 0; k0 < DPAD; k0 += 16) {
        {
            int r = tid >> 1, h = tid & 1;
            const uint4* src = reinterpret_cast<const uint4*>(
                &g_A[(size_t)(m0 + r) * DPAD + k0 + 8 * h]);
            *reinterpret_cast<uint4*>(&sA[r * 16 + 8 * h]) = *src;
        }
        if (tid < 160) {
            int r = tid / 10, p = tid % 10;
            const uint4* src = reinterpret_cast<const uint4*>(
                &g_W1b[(size_t)(k0 + r) * H1 + n0 + 8 * p]);
            *reinterpret_cast<uint4*>(&sB[r * 80 + 8 * p]) = *src;
        }
        __syncthreads();

        wmma::fragment<wmma::matrix_a, 16, 16, 16, __nv_bfloat16, wmma::row_major> afrag;
        wmma::load_matrix_sync(afrag, &sA[w * 16 * 16], 16);
#pragma unroll
        for (int f = 0; f < 5; f++) {
            wmma::fragment<wmma::matrix_b, 16, 16, 16, __nv_bfloat16, wmma::row_major> bfrag;
            wmma::load_matrix_sync(bfrag, &sB[f * 16], 80);
            wmma::mma_sync(acc[f], afrag, bfrag, acc[f]);
        }
        __syncthreads();
    }
#pragma unroll
    for (int f = 0; f < 5; f++)
        wmma::store_matrix_sync(&g_X1[(size_t)(m0 + w * 16) * H1 + n0 + f * 16],
                                acc[f], H1, wmma::mem_row_major);
}

// ---------------- K1b: per-element LIF1 -> spike bitmask ----------------
__global__ void k_lif1(const float* __restrict__ b1) {
    int idx = blockIdx.x * blockDim.x + threadIdx.x;
    if (idx >= BATCH * H1) return;
    int col = idx % H1;
    float x = g_X1[idx] + b1[col];

    // whole-warp skip: v_t <= x always; if x < 1 (with margin) no spike possible
    unsigned am = __activemask();
    if (__all_sync(am, x < 0.999999f)) { g_S1[idx] = 0u; return; }

    float v = 0.0f;
    unsigned word = 0u;
#pragma unroll
    for (int t = 0; t < TSTEPS; t++) {
        v = fmaf(x - v, 0.5f, v);
        if (v >= 1.0f) { word |= (1u << t); v = 0.0f; }
    }
    g_S1[idx] = word;
}

// ---------------- K_check: warp per row, provable no-L2-spike bound --------
__global__ __launch_bounds__(256) void k_check() {
    __shared__ float          s_c[H1];
    __shared__ unsigned short s_fid[8][H1];
    __shared__ unsigned       s_msk[8][H1];

    int tid  = threadIdx.x;
    int lane = tid & 31;
    int w    = tid >> 5;
    int row  = blockIdx.x * 8 + w;
    unsigned lmask = (1u << lane) - 1u;

    for (int i = tid; i < H1; i += 256) s_c[i] = g_c[i];
    __syncthreads();

    int nf = 0;
    for (int r = 0; r * 32 < H1; r++) {
        int i = r * 32 + lane;
        unsigned m = (i < H1) ? g_S1[(size_t)row * H1 + i] : 0u;
        unsigned bal = __ballot_sync(0xffffffffu, m != 0u);
        int pos = nf + __popc(bal & lmask);
        if (m != 0u) { s_fid[w][pos] = (unsigned short)i; s_msk[w][pos] = m; }
        nf += __popc(bal);
    }
    // lane = timestep; sum c_i over neurons firing at that timestep
    float acc = 0.0f;
    for (int q = 0; q < nf; q++) {
        unsigned m = s_msk[w][q];
        float c = s_c[s_fid[w][q]];
        if ((m >> lane) & 1u) acc += c;
    }
#pragma unroll
    for (int o = 16; o; o >>= 1) acc = fmaxf(acc, __shfl_xor_sync(0xffffffffu, acc, o));
    if (lane == 0)
        g_flag[row] = (g_b2max + acc < 1.0f) ? 0 : 1;
}

// ---------------- K_out: fast-path streaming output ----------------
__global__ void k_out(const float* __restrict__ action, float* __restrict__ out) {
    int idx = blockIdx.x * blockDim.x + threadIdx.x;
    if (idx >= BATCH * ADIM) return;
    int row = idx / ADIM;
    if (g_flag[row]) return;                    // slow row: k_snn writes it
    int k = idx - row * ADIM;
    float o = g_const[k] + action[idx];
    out[idx] = fminf(fmaxf(o, -1.0f), 1.0f);
}

// ---------------- K2: exact slow path (rare rows) ----------------
__global__ __launch_bounds__(320) void k_snn(const float* __restrict__ action,
                                             const float* __restrict__ W2,
                                             const float* __restrict__ b2,
                                             const float* __restrict__ W3,
                                             const float* __restrict__ b3,
                                             float* __restrict__ out) {
    int row = blockIdx.x;
    if (g_flag[row] == 0) return;

    __shared__ float          s_w2[CAPC * H2];
    __shared__ unsigned       s_mask1[H1];
    __shared__ unsigned short s_fire[H1];
    __shared__ unsigned short s_list1[TSTEPS][CAP1];
    __shared__ int            s_cnt1[TSTEPS];
    __shared__ unsigned       s_mask2[H2];
    __shared__ unsigned short s_list2[TSTEPS][CAP2];
    __shared__ int            s_cnt2[TSTEPS];
    __shared__ int            s_nf;

    int tid  = threadIdx.x;
    int lane = tid & 31;
    int w    = tid >> 5;
    unsigned lmask = (1u << lane) - 1u;

    for (int i = tid; i < H1; i += 320)
        s_mask1[i] = g_S1[(size_t)row * H1 + i];
    __syncthreads();

    if (w == 0) {
        int nf = 0;
        for (int c = 0; c * 32 < H1; c++) {
            int i = c * 32 + lane;
            unsigned m = (i < H1) ? s_mask1[i] : 0u;
            int pred = (m != 0u);
            unsigned bal = __ballot_sync(0xffffffffu, pred);
            int pos = nf + __popc(bal & lmask);
            if (pred) s_fire[pos] = (unsigned short)i;
            nf += __popc(bal);
        }
        if (lane == 0) s_nf = nf;
    }
    __syncthreads();
    int nf = s_nf;
    int ncache = nf < CAPC ? nf : CAPC;

    for (int idx = tid; idx < ncache * H2; idx += 320) {
        int q = idx / H2;
        int j = idx - q * H2;
        s_w2[q * H2 + j] = W2[(size_t)s_fire[q] * H2 + j];
    }

    for (int t = w; t < TSTEPS; t += 10) {
        int cnt = 0;
        for (int c = 0; c * 32 < nf; c++) {
            int qi = c * 32 + lane;
            int pred = 0; unsigned short entry = 0;
            if (qi < nf) {
                int i = s_fire[qi];
                if ((s_mask1[i] >> t) & 1u) {
                    pred = 1;
                    entry = (qi < CAPC) ? (unsigned short)qi
                                        : (unsigned short)(256 + i);
                }
            }
            unsigned bal = __ballot_sync(0xffffffffu, pred);
            int pos = cnt + __popc(bal & lmask);
            if (pred && pos < CAP1) s_list1[t][pos] = entry;
            cnt += __popc(bal);
        }
        s_cnt1[t] = cnt < CAP1 ? cnt : CAP1;
    }
    __syncthreads();

    if (tid < H2) {
        int j = tid;
        float b2j = b2[j];
        float v2 = 0.0f;
        unsigned mask2 = 0u;
        for (int t = 0; t < TSTEPS; t++) {
            float x2 = b2j;
            int n = s_cnt1[t];
            for (int q = 0; q < n; q++) {
                int e = s_list1[t][q];
                float wv = (e < CAPC) ? s_w2[e * H2 + j]
                                      : W2[(size_t)(e - 256) * H2 + j];
                x2 += wv;
            }
            v2 += (x2 - v2) * 0.5f;
            if (v2 >= 1.0f) { mask2 |= (1u << t); v2 = 0.0f; }
        }
        s_mask2[j] = mask2;
    }
    __syncthreads();

    for (int t = w; t < TSTEPS; t += 10) {
        int cnt = 0;
        for (int c = 0; c * 32 < H2; c++) {
            int j = c * 32 + lane;
            int pred = 0;
            if (j < H2) pred = (int)((s_mask2[j] >> t) & 1u);
            unsigned bal = __ballot_sync(0xffffffffu, pred);
            int pos = cnt + __popc(bal & lmask);
            if (pred && pos < CAP2) s_list2[t][pos] = (unsigned short)j;
            cnt += __popc(bal);
        }
        s_cnt2[t] = cnt < CAP2 ? cnt : CAP2;
    }
    __syncthreads();

    if (tid < ADIM) {
        int k = tid;
        float b3k = b3[k];
        float v3 = 0.0f, vmax = -3.4e38f;
        for (int t = 0; t < TSTEPS; t++) {
            float x3 = b3k;
            int n = s_cnt2[t];
            for (int q = 0; q < n; q++) {
                int j = s_list2[t][q];
                x3 += W3[j * ADIM + k];
            }
            v3 += (x3 - v3) * 0.5f;
            vmax = fmaxf(vmax, v3);
        }
        float a = 0.05f * tanhf(vmax);
        float o = a + action[(size_t)row * ADIM + k];
        o = fminf(fmaxf(o, -1.0f), 1.0f);
        out[(size_t)row * ADIM + k] = o;
    }
}

// ---------------- launch ----------------
extern "C" void kernel_launch(void* const* d_in, const int* in_sizes, int n_in,
                              void* d_out, int out_size) {
    (void)in_sizes; (void)n_in; (void)out_size;
    const float* state  = (const float*)d_in[0];
    const float* action = (const float*)d_in[1];
    const float* W1     = (const float*)d_in[2];
    const float* b1     = (const float*)d_in[3];
    const float* W2     = (const float*)d_in[4];
    const float* b2     = (const float*)d_in[5];
    const float* W3     = (const float*)d_in[6];
    const float* b3     = (const float*)d_in[7];
    float* out = (float*)d_out;

    k_pack_input<<<(BATCH * DPAD + 255) / 256, 256>>>(state, action);
    k_pack_w1<<<(DPAD * H1 + 255) / 256, 256>>>(W1);
    k_prep<<<H1 + 1, 32>>>(W2, b2, b3);

    dim3 g1(5, 64);
    k_gemm1<<<g1, 256>>>();

    k_lif1<<<(BATCH * H1 + 255) / 256, 256>>>(b1);
    k_check<<<BATCH / 8, 256>>>();
    k_out<<<(BATCH * ADIM + 255) / 256, 256>>>(action, out);
    k_snn<<<BATCH, 320>>>(action, W2, b2, W3, b3, out);
}

// round 3
// speedup vs baseline: 2.6180x; 1.0121x over previous
#include <cuda_runtime.h>
#include <cuda_bf16.h>
#include <mma.h>
#include <math.h>

using namespace nvcuda;

#define BATCH 8192
#define SDIM  376
#define ADIM  17
#define DIN   393
#define DPAD  416      // padded K, 13 chunks of 32
#define KCH   32
#define NCH   13
#define H1    400
#define H2    300
#define TSTEPS 32

#define CAPC  24
#define CAP1  96
#define CAP2  96

// ---------------- static device scratch ----------------
__device__ __align__(16) __nv_bfloat16 g_A[(size_t)BATCH * DPAD];
__device__ __align__(16) __nv_bfloat16 g_W1b[(size_t)DPAD * H1];
__device__ __align__(16) unsigned      g_S1[(size_t)BATCH * H1];
__device__ float g_c[H1];         // c_i = max_j W2[i,j]
__device__ float g_b2max;
__device__ float g_const[ADIM];   // 0.05*tanh(vmax(b3_k))
__device__ int   g_flag[BATCH];

// ---------------- cp.async helpers ----------------
__device__ __forceinline__ void cp16(void* dst, const void* src) {
    unsigned d = (unsigned)__cvta_generic_to_shared(dst);
    asm volatile("cp.async.cg.shared.global [%0], [%1], 16;\n" :: "r"(d), "l"(src));
}
__device__ __forceinline__ void cp_commit() {
    asm volatile("cp.async.commit_group;\n");
}
template<int N> __device__ __forceinline__ void cp_wait() {
    asm volatile("cp.async.wait_group %0;\n" :: "n"(N));
}

// ---------------- K0a: pack [state|action|0pad] -> bf16 ----------------
__global__ void k_pack_input(const float* __restrict__ state,
                             const float* __restrict__ action) {
    int idx = blockIdx.x * blockDim.x + threadIdx.x;     // one per 8 cols
    if (idx >= BATCH * (DPAD / 8)) return;
    int row = idx / (DPAD / 8);
    int c0  = (idx - row * (DPAD / 8)) * 8;
    __nv_bfloat16 v[8];
#pragma unroll
    for (int u = 0; u < 8; u++) {
        int col = c0 + u;
        float f = 0.0f;
        if (col < SDIM)      f = state[(size_t)row * SDIM + col];
        else if (col < DIN)  f = action[(size_t)row * ADIM + (col - SDIM)];
        v[u] = __float2bfloat16(f);
    }
    *reinterpret_cast<uint4*>(&g_A[(size_t)row * DPAD + c0]) =
        *reinterpret_cast<uint4*>(v);
}

// ---------------- K0b: pack W1 (393x400 -> 416x400, zero pad rows) -------
__global__ void k_pack_w1(const float* __restrict__ W1) {
    int idx = blockIdx.x * blockDim.x + threadIdx.x;
    if (idx >= DPAD * H1) return;
    int r = idx / H1;
    int c = idx - r * H1;
    g_W1b[idx] = __float2bfloat16(r < DIN ? W1[(size_t)r * H1 + c] : 0.0f);
}

// ---------------- K_prep: c_i, b2max, const_k ----------------
__global__ void k_prep(const float* __restrict__ W2,
                       const float* __restrict__ b2,
                       const float* __restrict__ b3) {
    int bid  = blockIdx.x;
    int lane = threadIdx.x;
    if (bid < H1) {
        float m = -3.4e38f;
        for (int j = lane; j < H2; j += 32)
            m = fmaxf(m, W2[(size_t)bid * H2 + j]);
#pragma unroll
        for (int o = 16; o; o >>= 1) m = fmaxf(m, __shfl_xor_sync(0xffffffffu, m, o));
        if (lane == 0) g_c[bid] = m;
    } else {
        float m = -3.4e38f;
        for (int j = lane; j < H2; j += 32) m = fmaxf(m, b2[j]);
#pragma unroll
        for (int o = 16; o; o >>= 1) m = fmaxf(m, __shfl_xor_sync(0xffffffffu, m, o));
        if (lane == 0) g_b2max = m;
        if (lane < ADIM) {
            float b = b3[lane];
            float vmax = (b > 0.0f) ? b : 0.5f * b;   // monotone v3 = b3*(1-2^-t)
            g_const[lane] = 0.05f * tanhf(vmax);
        }
    }
}

// ---------------- K1: fused GEMM (bf16 wmma, cp.async dbuf) + bias + LIF1 ---
// grid (5, 64); tile 128x80; K chunks of 32, double-buffered.
// smem union: load buffers (26624B) overlap with fp32 stage (40960B).
__global__ __launch_bounds__(256) void k_gemm_lif(const float* __restrict__ b1) {
    __shared__ __align__(16) unsigned char smem_raw[40960];

    __nv_bfloat16* sA0 = reinterpret_cast<__nv_bfloat16*>(smem_raw);            // 128*32
    __nv_bfloat16* sA1 = sA0 + 128 * KCH;
    __nv_bfloat16* sB0 = sA1 + 128 * KCH;                                       // 32*80
    __nv_bfloat16* sB1 = sB0 + KCH * 80;
    __nv_bfloat16* sAp[2] = { sA0, sA1 };
    __nv_bfloat16* sBp[2] = { sB0, sB1 };

    const int tid = threadIdx.x;
    const int w   = tid >> 5;
    const int m0  = blockIdx.y * 128;
    const int n0  = blockIdx.x * 80;

    wmma::fragment<wmma::accumulator, 16, 16, 16, float> acc[5];
#pragma unroll
    for (int f = 0; f < 5; f++) wmma::fill_fragment(acc[f], 0.0f);

    auto load_chunk = [&](int c, int b) {
        // A: 128 rows x 32 cols bf16 = 512 x 16B
        int t = tid;
#pragma unroll
        for (int rep = 0; rep < 2; rep++, t += 256) {
            int r = t >> 2, h = t & 3;
            cp16(sAp[b] + r * KCH + 8 * h,
                 &g_A[(size_t)(m0 + r) * DPAD + c * KCH + 8 * h]);
        }
        // B: 32 rows x 80 cols bf16 = 320 x 16B
        t = tid;
        if (t < 320) {
            int r = t / 10, p = t - r * 10;
            cp16(sBp[b] + r * 80 + 8 * p,
                 &g_W1b[(size_t)(c * KCH + r) * H1 + n0 + 8 * p]);
        }
        t = tid + 256;
        if (t < 320) {
            int r = t / 10, p = t - r * 10;
            cp16(sBp[b] + r * 80 + 8 * p,
                 &g_W1b[(size_t)(c * KCH + r) * H1 + n0 + 8 * p]);
        }
    };

    load_chunk(0, 0);
    cp_commit();

    for (int c = 0; c < NCH; c++) {
        int cur = c & 1;
        if (c + 1 < NCH) {
            load_chunk(c + 1, cur ^ 1);
            cp_commit();
            cp_wait<1>();
        } else {
            cp_wait<0>();
        }
        __syncthreads();

#pragma unroll
        for (int ks = 0; ks < 2; ks++) {
            wmma::fragment<wmma::matrix_a, 16, 16, 16, __nv_bfloat16, wmma::row_major> afrag;
            wmma::load_matrix_sync(afrag, sAp[cur] + (w * 16) * KCH + ks * 16, KCH);
#pragma unroll
            for (int f = 0; f < 5; f++) {
                wmma::fragment<wmma::matrix_b, 16, 16, 16, __nv_bfloat16, wmma::row_major> bfrag;
                wmma::load_matrix_sync(bfrag, sBp[cur] + (ks * 16) * 80 + f * 16, 80);
                wmma::mma_sync(acc[f], afrag, bfrag, acc[f]);
            }
        }
        __syncthreads();
    }

    // epilogue: stage fp32 results (reuse smem), then bias + LIF -> bitmask
    float* stage = reinterpret_cast<float*>(smem_raw);   // 128*80 fp32 = 40960B
#pragma unroll
    for (int f = 0; f < 5; f++)
        wmma::store_matrix_sync(&stage[(w * 16) * 80 + f * 16], acc[f], 80,
                                wmma::mem_row_major);
    __syncthreads();

    for (int idx = tid; idx < 128 * 80; idx += 256) {
        int r  = idx / 80;
        int cc = idx - r * 80;
        float x = stage[idx] + b1[n0 + cc];
        unsigned word = 0u;
        if (x >= 0.999999f) {            // v_t < x, so x<1 can never spike
            float v = 0.0f;
#pragma unroll
            for (int t = 0; t < TSTEPS; t++) {
                v = fmaf(x - v, 0.5f, v);
                if (v >= 1.0f) { word |= (1u << t); v = 0.0f; }
            }
        }
        g_S1[(size_t)(m0 + r) * H1 + n0 + cc] = word;
    }
}

// ---------------- K_check_out: flag + fast-path output, warp per row -------
__global__ __launch_bounds__(256) void k_check_out(const float* __restrict__ action,
                                                   float* __restrict__ out) {
    __shared__ float          s_c[H1];
    __shared__ float          s_const[32];
    __shared__ unsigned short s_fid[8][H1];
    __shared__ unsigned       s_msk[8][H1];

    int tid  = threadIdx.x;
    int lane = tid & 31;
    int w    = tid >> 5;
    int row  = blockIdx.x * 8 + w;
    unsigned lmask = (1u << lane) - 1u;

    for (int i = tid; i < H1; i += 256) s_c[i] = g_c[i];
    if (tid < ADIM) s_const[tid] = g_const[tid];
    __syncthreads();

    // compact firing neurons of this row
    int nf = 0;
    for (int r = 0; r * 32 < H1; r++) {
        int i = r * 32 + lane;
        unsigned m = (i < H1) ? g_S1[(size_t)row * H1 + i] : 0u;
        unsigned bal = __ballot_sync(0xffffffffu, m != 0u);
        int pos = nf + __popc(bal & lmask);
        if (m != 0u) { s_fid[w][pos] = (unsigned short)i; s_msk[w][pos] = m; }
        nf += __popc(bal);
    }
    // lane = timestep; accumulate c_i over firing neurons at that timestep
    float acc = 0.0f;
    for (int q = 0; q < nf; q++) {
        unsigned m = s_msk[w][q];
        float c = s_c[s_fid[w][q]];
        if ((m >> lane) & 1u) acc += c;
    }
#pragma unroll
    for (int o = 16; o; o >>= 1) acc = fmaxf(acc, __shfl_xor_sync(0xffffffffu, acc, o));
    int flag = (g_b2max + __shfl_sync(0xffffffffu, acc, 0) < 1.0f) ? 0 : 1;
    if (lane == 0) g_flag[row] = flag;

    if (!flag && lane < ADIM) {
        float o = s_const[lane] + action[(size_t)row * ADIM + lane];
        out[(size_t)row * ADIM + lane] = fminf(fmaxf(o, -1.0f), 1.0f);
    }
}

// ---------------- K2: exact slow path (rare rows) ----------------
__global__ __launch_bounds__(320) void k_snn(const float* __restrict__ action,
                                             const float* __restrict__ W2,
                                             const float* __restrict__ b2,
                                             const float* __restrict__ W3,
                                             const float* __restrict__ b3,
                                             float* __restrict__ out) {
    int row = blockIdx.x;
    if (g_flag[row] == 0) return;

    __shared__ float          s_w2[CAPC * H2];
    __shared__ unsigned       s_mask1[H1];
    __shared__ unsigned short s_fire[H1];
    __shared__ unsigned short s_list1[TSTEPS][CAP1];
    __shared__ int            s_cnt1[TSTEPS];
    __shared__ unsigned       s_mask2[H2];
    __shared__ unsigned short s_list2[TSTEPS][CAP2];
    __shared__ int            s_cnt2[TSTEPS];
    __shared__ int            s_nf;

    int tid  = threadIdx.x;
    int lane = tid & 31;
    int w    = tid >> 5;
    unsigned lmask = (1u << lane) - 1u;

    for (int i = tid; i < H1; i += 320)
        s_mask1[i] = g_S1[(size_t)row * H1 + i];
    __syncthreads();

    if (w == 0) {
        int nf = 0;
        for (int c = 0; c * 32 < H1; c++) {
            int i = c * 32 + lane;
            unsigned m = (i < H1) ? s_mask1[i] : 0u;
            int pred = (m != 0u);
            unsigned bal = __ballot_sync(0xffffffffu, pred);
            int pos = nf + __popc(bal & lmask);
            if (pred) s_fire[pos] = (unsigned short)i;
            nf += __popc(bal);
        }
        if (lane == 0) s_nf = nf;
    }
    __syncthreads();
    int nf = s_nf;
    int ncache = nf < CAPC ? nf : CAPC;

    for (int idx = tid; idx < ncache * H2; idx += 320) {
        int q = idx / H2;
        int j = idx - q * H2;
        s_w2[q * H2 + j] = W2[(size_t)s_fire[q] * H2 + j];
    }

    for (int t = w; t < TSTEPS; t += 10) {
        int cnt = 0;
        for (int c = 0; c * 32 < nf; c++) {
            int qi = c * 32 + lane;
            int pred = 0; unsigned short entry = 0;
            if (qi < nf) {
                int i = s_fire[qi];
                if ((s_mask1[i] >> t) & 1u) {
                    pred = 1;
                    entry = (qi < CAPC) ? (unsigned short)qi
                                        : (unsigned short)(256 + i);
                }
            }
            unsigned bal = __ballot_sync(0xffffffffu, pred);
            int pos = cnt + __popc(bal & lmask);
            if (pred && pos < CAP1) s_list1[t][pos] = entry;
            cnt += __popc(bal);
        }
        s_cnt1[t] = cnt < CAP1 ? cnt : CAP1;
    }
    __syncthreads();

    if (tid < H2) {
        int j = tid;
        float b2j = b2[j];
        float v2 = 0.0f;
        unsigned mask2 = 0u;
        for (int t = 0; t < TSTEPS; t++) {
            float x2 = b2j;
            int n = s_cnt1[t];
            for (int q = 0; q < n; q++) {
                int e = s_list1[t][q];
                float wv = (e < CAPC) ? s_w2[e * H2 + j]
                                      : W2[(size_t)(e - 256) * H2 + j];
                x2 += wv;
            }
            v2 += (x2 - v2) * 0.5f;
            if (v2 >= 1.0f) { mask2 |= (1u << t); v2 = 0.0f; }
        }
        s_mask2[j] = mask2;
    }
    __syncthreads();

    for (int t = w; t < TSTEPS; t += 10) {
        int cnt = 0;
        for (int c = 0; c * 32 < H2; c++) {
            int j = c * 32 + lane;
            int pred = 0;
            if (j < H2) pred = (int)((s_mask2[j] >> t) & 1u);
            unsigned bal = __ballot_sync(0xffffffffu, pred);
            int pos = cnt + __popc(bal & lmask);
            if (pred && pos < CAP2) s_list2[t][pos] = (unsigned short)j;
            cnt += __popc(bal);
        }
        s_cnt2[t] = cnt < CAP2 ? cnt : CAP2;
    }
    __syncthreads();

    if (tid < ADIM) {
        int k = tid;
        float b3k = b3[k];
        float v3 = 0.0f, vmax = -3.4e38f;
        for (int t = 0; t < TSTEPS; t++) {
            float x3 = b3k;
            int n = s_cnt2[t];
            for (int q = 0; q < n; q++) {
                int j = s_list2[t][q];
                x3 += W3[j * ADIM + k];
            }
            v3 += (x3 - v3) * 0.5f;
            vmax = fmaxf(vmax, v3);
        }
        float a = 0.05f * tanhf(vmax);
        float o = a + action[(size_t)row * ADIM + k];
        o = fminf(fmaxf(o, -1.0f), 1.0f);
        out[(size_t)row * ADIM + k] = o;
    }
}

// ---------------- launch ----------------
extern "C" void kernel_launch(void* const* d_in, const int* in_sizes, int n_in,
                              void* d_out, int out_size) {
    (void)in_sizes; (void)n_in; (void)out_size;
    const float* state  = (const float*)d_in[0];
    const float* action = (const float*)d_in[1];
    const float* W1     = (const float*)d_in[2];
    const float* b1     = (const float*)d_in[3];
    const float* W2     = (const float*)d_in[4];
    const float* b2     = (const float*)d_in[5];
    const float* W3     = (const float*)d_in[6];
    const float* b3     = (const float*)d_in[7];
    float* out = (float*)d_out;

    k_pack_input<<<(BATCH * (DPAD / 8) + 255) / 256, 256>>>(state, action);
    k_pack_w1<<<(DPAD * H1 + 255) / 256, 256>>>(W1);
    k_prep<<<H1 + 1, 32>>>(W2, b2, b3);

    dim3 g1(5, 64);
    k_gemm_lif<<<g1, 256>>>(b1);

    k_check_out<<<BATCH / 8, 256>>>(action, out);
    k_snn<<<BATCH, 320>>>(action, W2, b2, W3, b3, out);
}